// round 14
// baseline (speedup 1.0000x reference)
#include <cuda_runtime.h>
#include <cuda_fp16.h>
#include <cstdint>

// Problem constants
#define D_MODEL 1024
#define NH      16
#define DH      64
#define KEIG    16
#define M_TOK   16384          // B * N = 4 * 4096
#define NC      3072           // 3 * NH * DH
#define NCQK    2048           // Qf|Kf columns kept in fp32
#define KDIM    1024

// GEMM tiling
#define BM 128
#define BN 128
#define BKC 32                 // K per chunk
#define NCH (KDIM / BKC)       // 32 chunks

// QK kernel: 3-stage, 32KB/stage (Ah|Al|Bh|Bl)
#define STAGE_QK 32768
#define SMEM_QK  (3 * STAGE_QK)
// V kernel: 4-stage, 16KB/stage (Ah|Bh)
#define STAGE_V  16384
#define SMEM_V   (4 * STAGE_V)

// 64B-row swizzle
#define SWZ64(o) ((uint32_t)(o) ^ ((((uint32_t)(o)) >> 3) & 0x30u))

// ---------------------------------------------------------------------------
// Device scratch
// ---------------------------------------------------------------------------
__device__ float  g_Wc[(size_t)KDIM * NC];      // eigen-folded weights fp32 [k][n]
__device__ float  g_bc[NC];                      // eigen-folded bias
__device__ float  g_QKf[(size_t)M_TOK * NCQK];  // Qf|Kf fp32 per token
__device__ __half g_Vh[(size_t)M_TOK * 1024];   // Vf fp16 per token
__device__ __half g_xh[(size_t)M_TOK * KDIM];   // x hi fp16    [m][k]
__device__ __half g_xl[(size_t)M_TOK * KDIM];   // x lo fp16    [m][k]
__device__ __half g_Wth[(size_t)NC * KDIM];     // W^T hi fp16  [n][k]
__device__ __half g_Wtl[(size_t)NC * KDIM];     // W^T lo fp16  [n][k]

// ---------------------------------------------------------------------------
// PTX helpers (baseline PTX only)
// ---------------------------------------------------------------------------
static __device__ __forceinline__ uint32_t smem_u32(const void* p) {
    uint32_t a;
    asm("{ .reg .u64 t; cvta.to.shared.u64 t, %1; cvt.u32.u64 %0, t; }"
        : "=r"(a) : "l"(p));
    return a;
}
static __device__ __forceinline__ void cp16(uint32_t saddr, const void* g) {
    asm volatile("cp.async.cg.shared.global [%0], [%1], 16;"
                 :: "r"(saddr), "l"(g));
}
static __device__ __forceinline__ void cp_commit() {
    asm volatile("cp.async.commit_group;" ::: "memory");
}
template <int N>
static __device__ __forceinline__ void cp_wait() {
    asm volatile("cp.async.wait_group %0;" :: "n"(N) : "memory");
}
static __device__ __forceinline__ void ldsm4(uint32_t* r, uint32_t addr) {
    asm volatile("ldmatrix.sync.aligned.m8n8.x4.shared.b16 {%0,%1,%2,%3}, [%4];"
                 : "=r"(r[0]), "=r"(r[1]), "=r"(r[2]), "=r"(r[3])
                 : "r"(addr));
}
static __device__ __forceinline__ void mma16816(float* d, const uint32_t* a,
                                                uint32_t b0, uint32_t b1) {
    asm volatile(
        "mma.sync.aligned.m16n8k16.row.col.f32.f16.f16.f32 "
        "{%0,%1,%2,%3}, {%4,%5,%6,%7}, {%8,%9}, {%0,%1,%2,%3};"
        : "+f"(d[0]), "+f"(d[1]), "+f"(d[2]), "+f"(d[3])
        : "r"(a[0]), "r"(a[1]), "r"(a[2]), "r"(a[3]), "r"(b0), "r"(b1));
}

// ---------------------------------------------------------------------------
// Kernel A1: fold eigenvectors + filter weights into fused weights
// ---------------------------------------------------------------------------
__global__ __launch_bounds__(256)
void k_transform_w(const float* __restrict__ Wq,
                   const float* __restrict__ Wk,
                   const float* __restrict__ Wv,
                   const float* __restrict__ E,
                   const float* __restrict__ fw)
{
    __shared__ float Ws[1024];
    __shared__ float Ek[16][16];

    const int r = blockIdx.x;
    const int s = blockIdx.y;
    const int tid = threadIdx.x;
    const float* W = (s == 0) ? Wq : (s == 1) ? Wk : Wv;

    ((float4*)Ws)[tid] = ((const float4*)(W + (size_t)r * 1024))[tid];
    {
        int h = tid >> 4, k = tid & 15;
        Ek[h][k] = E[tid] * fw[k];
    }
    __syncthreads();

    const int d = tid & 63;
    float* dst = g_Wc + (size_t)r * NC + s * 1024;
#pragma unroll
    for (int j = 0; j < 4; j++) {
        int k = (tid >> 6) + j * 4;
        float acc = 0.f;
#pragma unroll
        for (int h = 0; h < NH; h++)
            acc = fmaf(Ek[h][k], Ws[h * 64 + d], acc);
        dst[k * 64 + d] = acc;
    }
}

__global__ void k_transform_b(const float* __restrict__ bq,
                              const float* __restrict__ bk,
                              const float* __restrict__ bv,
                              const float* __restrict__ E,
                              const float* __restrict__ fw)
{
    int j = blockIdx.x * blockDim.x + threadIdx.x;
    if (j >= NC) return;
    int s = j >> 10;
    int c = j & 1023;
    int k = c >> 6;
    int d = c & 63;
    const float* b = (s == 0) ? bq : (s == 1) ? bk : bv;
    float acc = 0.f;
#pragma unroll
    for (int h = 0; h < NH; h++)
        acc = fmaf(E[h * KEIG + k], b[h * DH + d], acc);
    g_bc[j] = acc * fw[k];
}

// ---------------------------------------------------------------------------
// Kernel A2: split x into fp16 hi/lo
// ---------------------------------------------------------------------------
__global__ __launch_bounds__(256)
void k_split_x(const float* __restrict__ x)
{
    size_t i = ((size_t)blockIdx.x * 256 + threadIdx.x) * 4;
    float4 v = *(const float4*)(x + i);
    __half h0 = __float2half_rn(v.x);
    __half h1 = __float2half_rn(v.y);
    __half h2 = __float2half_rn(v.z);
    __half h3 = __float2half_rn(v.w);
    __half l0 = __float2half_rn(v.x - __half2float(h0));
    __half l1 = __float2half_rn(v.y - __half2float(h1));
    __half l2 = __float2half_rn(v.z - __half2float(h2));
    __half l3 = __float2half_rn(v.w - __half2float(h3));
    uint2 ph, pl;
    ph.x = ((uint32_t)__half_as_ushort(h1) << 16) | __half_as_ushort(h0);
    ph.y = ((uint32_t)__half_as_ushort(h3) << 16) | __half_as_ushort(h2);
    pl.x = ((uint32_t)__half_as_ushort(l1) << 16) | __half_as_ushort(l0);
    pl.y = ((uint32_t)__half_as_ushort(l3) << 16) | __half_as_ushort(l2);
    *(uint2*)(g_xh + i) = ph;
    *(uint2*)(g_xl + i) = pl;
}

// ---------------------------------------------------------------------------
// Kernel A3: transpose g_Wc [k][n] -> fp16 hi/lo [n][k]
// ---------------------------------------------------------------------------
__global__ __launch_bounds__(256)
void k_wsplit()
{
    __shared__ float t[32][33];
    int tx = threadIdx.x & 31;
    int ty = threadIdx.x >> 5;
    int n0 = blockIdx.x * 32;
    int k0 = blockIdx.y * 32;
#pragma unroll
    for (int i = 0; i < 32; i += 8)
        t[ty + i][tx] = g_Wc[(size_t)(k0 + ty + i) * NC + (n0 + tx)];
    __syncthreads();
#pragma unroll
    for (int i = 0; i < 32; i += 8) {
        int n = n0 + ty + i;
        int k = k0 + tx;
        float v = t[tx][ty + i];
        __half h = __float2half_rn(v);
        __half l = __float2half_rn(v - __half2float(h));
        g_Wth[(size_t)n * KDIM + k] = h;
        g_Wtl[(size_t)n * KDIM + k] = l;
    }
}

// ---------------------------------------------------------------------------
// Kernel B1: Q,K GEMM — fp16 3-pass (xh*Wh + xh*Wl + xl*Wh), 3-stage pipeline.
// Writes fp32 to g_QKf (stride 2048).
// ---------------------------------------------------------------------------
__global__ __launch_bounds__(256, 2)
void k_gemm_qk()
{
    extern __shared__ char smem[];
    const uint32_t sb = smem_u32(smem);
    const int tid  = threadIdx.x;
    const int lane = tid & 31;
    const int wid  = tid >> 5;
    const int bm = blockIdx.y * BM;
    const int bn = blockIdx.x * BN;

    const int mbase = (wid >> 2) * 64;
    const int nbase = (wid & 3) * 32;

    const __half* xh = g_xh  + (size_t)bm * KDIM;
    const __half* xl = g_xl  + (size_t)bm * KDIM;
    const __half* wh = g_Wth + (size_t)bn * KDIM;
    const __half* wl = g_Wtl + (size_t)bn * KDIM;

    auto load_chunk = [&](int st, int c) {
        uint32_t base = sb + st * STAGE_QK;
        size_t koff = (size_t)c * BKC;
#pragma unroll
        for (int it = 0; it < 2; it++) {
            int idx = tid + it * 256;
            int row = idx >> 2, v = idx & 3;
            uint32_t so = SWZ64(row * 64 + v * 16);
            size_t go = (size_t)row * KDIM + koff + v * 8;
            cp16(base +         so, xh + go);
            cp16(base +  8192 + so, xl + go);
            cp16(base + 16384 + so, wh + go);
            cp16(base + 24576 + so, wl + go);
        }
    };

    float acc[4][4][4];
#pragma unroll
    for (int i = 0; i < 4; i++)
#pragma unroll
        for (int j = 0; j < 4; j++)
#pragma unroll
            for (int r = 0; r < 4; r++) acc[i][j][r] = 0.f;

    load_chunk(0, 0); cp_commit();
    load_chunk(1, 1); cp_commit();

    const int a_m = (lane & 15);
    const int a_h = (lane >> 4);
    const int b_n = ((lane >> 4) << 3) + (lane & 7);
    const int b_h = ((lane >> 3) & 1);

    int st = 0;
    for (int c = 0; c < NCH; c++) {
        if (c + 2 < NCH) {
            int st2 = st + 2; if (st2 >= 3) st2 -= 3;
            load_chunk(st2, c + 2); cp_commit();
            cp_wait<2>();
        } else if (c + 1 < NCH) cp_wait<1>();
        else                    cp_wait<0>();
        __syncthreads();

        uint32_t base = sb + st * STAGE_QK;
        uint32_t sAh = base;
        uint32_t sAl = base + 8192;
        uint32_t sBh = base + 16384;
        uint32_t sBl = base + 24576;

#pragma unroll
        for (int ks = 0; ks < 2; ks++) {
            uint32_t ah[4][4], bh[2][4];
            int av = ks * 2 + a_h;
            int bv = ks * 2 + b_h;
#pragma unroll
            for (int mb = 0; mb < 4; mb++) {
                int m = mbase + mb * 16 + a_m;
                ldsm4(ah[mb], sAh + SWZ64(m * 64 + av * 16));
            }
#pragma unroll
            for (int nb2 = 0; nb2 < 2; nb2++) {
                int n = nbase + nb2 * 16 + b_n;
                ldsm4(bh[nb2], sBh + SWZ64(n * 64 + bv * 16));
            }
            // pass 1: xh * Wh
#pragma unroll
            for (int mb = 0; mb < 4; mb++)
#pragma unroll
                for (int nb = 0; nb < 4; nb++) {
                    const uint32_t* f = &bh[nb >> 1][(nb & 1) * 2];
                    mma16816(acc[mb][nb], ah[mb], f[0], f[1]);
                }
            // pass 2: xh * Wl
            uint32_t bl[2][4];
#pragma unroll
            for (int nb2 = 0; nb2 < 2; nb2++) {
                int n = nbase + nb2 * 16 + b_n;
                ldsm4(bl[nb2], sBl + SWZ64(n * 64 + bv * 16));
            }
#pragma unroll
            for (int mb = 0; mb < 4; mb++)
#pragma unroll
                for (int nb = 0; nb < 4; nb++) {
                    const uint32_t* f = &bl[nb >> 1][(nb & 1) * 2];
                    mma16816(acc[mb][nb], ah[mb], f[0], f[1]);
                }
            // pass 3: xl * Wh
            uint32_t al[4][4];
#pragma unroll
            for (int mb = 0; mb < 4; mb++) {
                int m = mbase + mb * 16 + a_m;
                ldsm4(al[mb], sAl + SWZ64(m * 64 + av * 16));
            }
#pragma unroll
            for (int mb = 0; mb < 4; mb++)
#pragma unroll
                for (int nb = 0; nb < 4; nb++) {
                    const uint32_t* f = &bh[nb >> 1][(nb & 1) * 2];
                    mma16816(acc[mb][nb], al[mb], f[0], f[1]);
                }
        }
        __syncthreads();
        if (++st == 3) st = 0;
    }

#pragma unroll
    for (int mb = 0; mb < 4; mb++) {
        int row = bm + mbase + mb * 16 + (lane >> 2);
#pragma unroll
        for (int nb = 0; nb < 4; nb++) {
            int col = bn + nbase + nb * 8 + (lane & 3) * 2;
            float b0 = g_bc[col], b1 = g_bc[col + 1];
            float2 v0 = make_float2(acc[mb][nb][0] + b0, acc[mb][nb][1] + b1);
            float2 v1 = make_float2(acc[mb][nb][2] + b0, acc[mb][nb][3] + b1);
            *(float2*)(g_QKf + (size_t)row * NCQK + col) = v0;
            *(float2*)(g_QKf + (size_t)(row + 8) * NCQK + col) = v1;
        }
    }
}

// ---------------------------------------------------------------------------
// Kernel B2: V GEMM — fp16 single pass (xh*Wh), 4-stage pipeline, fp16 output.
// ---------------------------------------------------------------------------
__global__ __launch_bounds__(256, 2)
void k_gemm_v()
{
    extern __shared__ char smem[];
    const uint32_t sb = smem_u32(smem);
    const int tid  = threadIdx.x;
    const int lane = tid & 31;
    const int wid  = tid >> 5;
    const int bm = blockIdx.y * BM;
    const int bnv = blockIdx.x * BN;          // 0..896 within V block

    const int mbase = (wid >> 2) * 64;
    const int nbase = (wid & 3) * 32;

    const __half* xh = g_xh  + (size_t)bm * KDIM;
    const __half* wh = g_Wth + (size_t)(2048 + bnv) * KDIM;

    auto load_chunk = [&](int st, int c) {
        uint32_t base = sb + st * STAGE_V;
        size_t koff = (size_t)c * BKC;
#pragma unroll
        for (int it = 0; it < 2; it++) {
            int idx = tid + it * 256;
            int row = idx >> 2, v = idx & 3;
            uint32_t so = SWZ64(row * 64 + v * 16);
            size_t go = (size_t)row * KDIM + koff + v * 8;
            cp16(base +        so, xh + go);
            cp16(base + 8192 + so, wh + go);
        }
    };

    float acc[4][4][4];
#pragma unroll
    for (int i = 0; i < 4; i++)
#pragma unroll
        for (int j = 0; j < 4; j++)
#pragma unroll
            for (int r = 0; r < 4; r++) acc[i][j][r] = 0.f;

    load_chunk(0, 0); cp_commit();
    load_chunk(1, 1); cp_commit();
    load_chunk(2, 2); cp_commit();

    const int a_m = (lane & 15);
    const int a_h = (lane >> 4);
    const int b_n = ((lane >> 4) << 3) + (lane & 7);
    const int b_h = ((lane >> 3) & 1);

    int st = 0;
    for (int c = 0; c < NCH; c++) {
        if (c + 3 < NCH) {
            int st3 = st + 3; if (st3 >= 4) st3 -= 4;
            load_chunk(st3, c + 3); cp_commit();
            cp_wait<3>();
        } else if (c + 2 < NCH) cp_wait<2>();
        else if (c + 1 < NCH)   cp_wait<1>();
        else                    cp_wait<0>();
        __syncthreads();

        uint32_t base = sb + st * STAGE_V;
        uint32_t sA = base;
        uint32_t sB = base + 8192;

#pragma unroll
        for (int ks = 0; ks < 2; ks++) {
            uint32_t ah[4][4], bh[2][4];
            int av = ks * 2 + a_h;
            int bv = ks * 2 + b_h;
#pragma unroll
            for (int mb = 0; mb < 4; mb++) {
                int m = mbase + mb * 16 + a_m;
                ldsm4(ah[mb], sA + SWZ64(m * 64 + av * 16));
            }
#pragma unroll
            for (int nb2 = 0; nb2 < 2; nb2++) {
                int n = nbase + nb2 * 16 + b_n;
                ldsm4(bh[nb2], sB + SWZ64(n * 64 + bv * 16));
            }
#pragma unroll
            for (int mb = 0; mb < 4; mb++)
#pragma unroll
                for (int nb = 0; nb < 4; nb++) {
                    const uint32_t* f = &bh[nb >> 1][(nb & 1) * 2];
                    mma16816(acc[mb][nb], ah[mb], f[0], f[1]);
                }
        }
        __syncthreads();
        if (++st == 4) st = 0;
    }

    // Epilogue: bias + fp16 store to g_Vh (stride 1024)
#pragma unroll
    for (int mb = 0; mb < 4; mb++) {
        int row = bm + mbase + mb * 16 + (lane >> 2);
#pragma unroll
        for (int nb = 0; nb < 4; nb++) {
            int colv = bnv + nbase + nb * 8 + (lane & 3) * 2;
            float b0 = g_bc[2048 + colv], b1 = g_bc[2048 + colv + 1];
            __half2 h0 = __floats2half2_rn(acc[mb][nb][0] + b0, acc[mb][nb][1] + b1);
            __half2 h1 = __floats2half2_rn(acc[mb][nb][2] + b0, acc[mb][nb][3] + b1);
            *(__half2*)(g_Vh + (size_t)row * 1024 + colv) = h0;
            *(__half2*)(g_Vh + (size_t)(row + 8) * 1024 + colv) = h1;
        }
    }
}

// ---------------------------------------------------------------------------
// Kernel C: per-token spectral attention, 2 tokens/block, float4 smem ops.
// Q,K from g_QKf (fp32, stride 2048); V from g_Vh (fp16, stride 1024).
// ---------------------------------------------------------------------------
#define TPB 2
__global__ __launch_bounds__(256)
void k_attn(const float* __restrict__ E, float* __restrict__ out)
{
    __shared__ float sQ[TPB][KEIG][68];
    __shared__ float sK[TPB][KEIG][68];
    __shared__ float sV[TPB][KEIG][68];
    __shared__ float sS[TPB][KEIG][17];
    __shared__ float sO[TPB][KEIG][68];
    __shared__ float sE[NH * KEIG];

    const int tid  = threadIdx.x;
    const int tok0 = blockIdx.x * TPB;

    // Q,K: TPB*512 float4 (4/thread)
#pragma unroll
    for (int v = tid; v < TPB * 512; v += 256) {
        int t = v >> 9;
        int r = v & 511;
        int mat = r >> 8;             // 0=Q 1=K
        int e   = r & 255;
        int k = e >> 4, dv = e & 15;
        float4 val = ((const float4*)(g_QKf + (size_t)(tok0 + t) * NCQK + mat * 1024))[e];
        float* dst = (mat == 0) ? &sQ[t][k][dv * 4] : &sK[t][k][dv * 4];
        *(float4*)dst = val;
    }
    // V: TPB*256 uint2 (4 halves each, 2/thread)
#pragma unroll
    for (int v = tid; v < TPB * 256; v += 256) {
        int t = v >> 8;
        int e = v & 255;
        int k = e >> 4, dv = e & 15;
        uint2 p = ((const uint2*)(g_Vh + (size_t)(tok0 + t) * 1024))[e];
        float2 ab = __half22float2(*(__half2*)&p.x);
        float2 cd = __half22float2(*(__half2*)&p.y);
        *(float4*)&sV[t][k][dv * 4] = make_float4(ab.x, ab.y, cd.x, cd.y);
    }
    sE[tid] = E[tid];
    __syncthreads();

    {
        int t = tid >> 7;
        int u = tid & 127;
#pragma unroll
        for (int pp = 0; pp < 2; pp++) {
            int p = u + pp * 128;
            int k = p >> 4, l = p & 15;
            float acc = 0.f;
#pragma unroll
            for (int dv = 0; dv < 16; dv++) {
                float4 q = *(const float4*)&sQ[t][k][dv * 4];
                float4 c = *(const float4*)&sK[t][l][dv * 4];
                acc = fmaf(q.x, c.x, acc);
                acc = fmaf(q.y, c.y, acc);
                acc = fmaf(q.z, c.z, acc);
                acc = fmaf(q.w, c.w, acc);
            }
            sS[t][k][l] = acc * 0.125f;
        }
    }
    __syncthreads();

    if (tid < TPB * KEIG) {
        int t = tid >> 4, k = tid & 15;
        float m = sS[t][k][0];
#pragma unroll
        for (int l = 1; l < KEIG; l++) m = fmaxf(m, sS[t][k][l]);
        float e[KEIG];
        float sum = 0.f;
#pragma unroll
        for (int l = 0; l < KEIG; l++) { e[l] = __expf(sS[t][k][l] - m); sum += e[l]; }
        float inv = 1.f / sum;
#pragma unroll
        for (int l = 0; l < KEIG; l++) sS[t][k][l] = e[l] * inv;
    }
    __syncthreads();

    {
        int t = tid >> 7;
        int u = tid & 127;
#pragma unroll
        for (int pp = 0; pp < 2; pp++) {
            int p = u + pp * 128;
            int k = p >> 4, dv = p & 15;
            float4 acc = make_float4(0.f, 0.f, 0.f, 0.f);
#pragma unroll
            for (int l = 0; l < KEIG; l++) {
                float a = sS[t][k][l];
                float4 v = *(const float4*)&sV[t][l][dv * 4];
                acc.x = fmaf(a, v.x, acc.x);
                acc.y = fmaf(a, v.y, acc.y);
                acc.z = fmaf(a, v.z, acc.z);
                acc.w = fmaf(a, v.w, acc.w);
            }
            *(float4*)&sO[t][k][dv * 4] = acc;
        }
    }
    __syncthreads();

    {
        int t = tid >> 7;
        int u = tid & 127;
#pragma unroll
        for (int pp = 0; pp < 2; pp++) {
            int p = u + pp * 128;
            int h = p >> 4, dv = p & 15;
            float4 acc = make_float4(0.f, 0.f, 0.f, 0.f);
#pragma unroll
            for (int k = 0; k < KEIG; k++) {
                float a = sE[h * KEIG + k];
                float4 v = *(const float4*)&sO[t][k][dv * 4];
                acc.x = fmaf(a, v.x, acc.x);
                acc.y = fmaf(a, v.y, acc.y);
                acc.z = fmaf(a, v.z, acc.z);
                acc.w = fmaf(a, v.w, acc.w);
            }
            ((float4*)(out + (size_t)(tok0 + t) * (NH * DH)))[h * 16 + dv] = acc;
        }
    }
}

// ---------------------------------------------------------------------------
extern "C" void kernel_launch(void* const* d_in, const int* in_sizes, int n_in,
                              void* d_out, int out_size)
{
    const float* x  = (const float*)d_in[0];
    const float* Wq = (const float*)d_in[1];
    const float* bq = (const float*)d_in[2];
    const float* Wk = (const float*)d_in[3];
    const float* bk = (const float*)d_in[4];
    const float* Wv = (const float*)d_in[5];
    const float* bv = (const float*)d_in[6];
    const float* E  = (const float*)d_in[7];
    const float* fw = (const float*)d_in[8];
    float* out = (float*)d_out;

    cudaFuncSetAttribute(k_gemm_qk, cudaFuncAttributeMaxDynamicSharedMemorySize, SMEM_QK);
    cudaFuncSetAttribute(k_gemm_v,  cudaFuncAttributeMaxDynamicSharedMemorySize, SMEM_V);

    k_transform_w<<<dim3(KDIM, 3), 256>>>(Wq, Wk, Wv, E, fw);
    k_transform_b<<<(NC + 255) / 256, 256>>>(bq, bk, bv, E, fw);
    k_split_x<<<(M_TOK * KDIM / 4) / 256, 256>>>(x);
    k_wsplit<<<dim3(NC / 32, KDIM / 32), 256>>>();
    k_gemm_qk<<<dim3(NCQK / BN, M_TOK / BM), 256, SMEM_QK>>>();
    k_gemm_v<<<dim3(1024 / BN, M_TOK / BM), 256, SMEM_V>>>();
    k_attn<<<M_TOK / TPB, 256>>>(E, out);
}

// round 15
// speedup vs baseline: 1.0259x; 1.0259x over previous
#include <cuda_runtime.h>
#include <cuda_fp16.h>
#include <cstdint>

// Problem constants
#define D_MODEL 1024
#define NH      16
#define DH      64
#define KEIG    16
#define M_TOK   16384          // B * N = 4 * 4096
#define NC      3072           // 3 * NH * DH
#define NCQK    2048           // Qf|Kf columns kept in fp32
#define KDIM    1024

// GEMM tiling (mma.sync fp16 path)
#define BM 128
#define BN 128
#define BKC 32                 // K per chunk
#define NCH (KDIM / BKC)       // 32 chunks
#define STAGE 32768            // smem bytes per pipeline stage (4 tiles x 8KB)
#define GEMM_SMEM (2 * STAGE)  // 64 KB double buffered

// 64B-row swizzle
#define SWZ64(o) ((uint32_t)(o) ^ ((((uint32_t)(o)) >> 3) & 0x30u))

// ---------------------------------------------------------------------------
// Device scratch
// ---------------------------------------------------------------------------
__device__ float  g_Wc[(size_t)KDIM * NC];      // eigen-folded weights fp32 [k][n]
__device__ float  g_bc[NC];                      // eigen-folded bias
__device__ float  g_QKf[(size_t)M_TOK * NCQK];  // Qf|Kf fp32 per token
__device__ __half g_Vh[(size_t)M_TOK * 1024];   // Vf fp16 per token
__device__ __half g_xh[(size_t)M_TOK * KDIM];   // x hi fp16    [m][k]
__device__ __half g_xl[(size_t)M_TOK * KDIM];   // x lo fp16    [m][k]
__device__ __half g_Wth[(size_t)NC * KDIM];     // W^T hi fp16  [n][k]
__device__ __half g_Wtl[(size_t)NC * KDIM];     // W^T lo fp16  [n][k]

// ---------------------------------------------------------------------------
// PTX helpers (baseline PTX only — legal on non-'a' sm_103 target)
// ---------------------------------------------------------------------------
static __device__ __forceinline__ uint32_t smem_u32(const void* p) {
    uint32_t a;
    asm("{ .reg .u64 t; cvta.to.shared.u64 t, %1; cvt.u32.u64 %0, t; }"
        : "=r"(a) : "l"(p));
    return a;
}
static __device__ __forceinline__ void cp16(uint32_t saddr, const void* g) {
    asm volatile("cp.async.cg.shared.global [%0], [%1], 16;"
                 :: "r"(saddr), "l"(g));
}
static __device__ __forceinline__ void cp_commit() {
    asm volatile("cp.async.commit_group;" ::: "memory");
}
template <int N>
static __device__ __forceinline__ void cp_wait() {
    asm volatile("cp.async.wait_group %0;" :: "n"(N) : "memory");
}
static __device__ __forceinline__ void ldsm4(uint32_t* r, uint32_t addr) {
    asm volatile("ldmatrix.sync.aligned.m8n8.x4.shared.b16 {%0,%1,%2,%3}, [%4];"
                 : "=r"(r[0]), "=r"(r[1]), "=r"(r[2]), "=r"(r[3])
                 : "r"(addr));
}
static __device__ __forceinline__ void mma16816(float* d, const uint32_t* a,
                                                uint32_t b0, uint32_t b1) {
    asm volatile(
        "mma.sync.aligned.m16n8k16.row.col.f32.f16.f16.f32 "
        "{%0,%1,%2,%3}, {%4,%5,%6,%7}, {%8,%9}, {%0,%1,%2,%3};"
        : "+f"(d[0]), "+f"(d[1]), "+f"(d[2]), "+f"(d[3])
        : "r"(a[0]), "r"(a[1]), "r"(a[2]), "r"(a[3]), "r"(b0), "r"(b1));
}

// ---------------------------------------------------------------------------
// Kernel A1: fold eigenvectors + filter weights into fused weights
// ---------------------------------------------------------------------------
__global__ __launch_bounds__(256)
void k_transform_w(const float* __restrict__ Wq,
                   const float* __restrict__ Wk,
                   const float* __restrict__ Wv,
                   const float* __restrict__ E,
                   const float* __restrict__ fw)
{
    __shared__ float Ws[1024];
    __shared__ float Ek[16][16];

    const int r = blockIdx.x;
    const int s = blockIdx.y;
    const int tid = threadIdx.x;
    const float* W = (s == 0) ? Wq : (s == 1) ? Wk : Wv;

    ((float4*)Ws)[tid] = ((const float4*)(W + (size_t)r * 1024))[tid];
    {
        int h = tid >> 4, k = tid & 15;
        Ek[h][k] = E[tid] * fw[k];
    }
    __syncthreads();

    const int d = tid & 63;
    float* dst = g_Wc + (size_t)r * NC + s * 1024;
#pragma unroll
    for (int j = 0; j < 4; j++) {
        int k = (tid >> 6) + j * 4;
        float acc = 0.f;
#pragma unroll
        for (int h = 0; h < NH; h++)
            acc = fmaf(Ek[h][k], Ws[h * 64 + d], acc);
        dst[k * 64 + d] = acc;
    }
}

__global__ void k_transform_b(const float* __restrict__ bq,
                              const float* __restrict__ bk,
                              const float* __restrict__ bv,
                              const float* __restrict__ E,
                              const float* __restrict__ fw)
{
    int j = blockIdx.x * blockDim.x + threadIdx.x;
    if (j >= NC) return;
    int s = j >> 10;
    int c = j & 1023;
    int k = c >> 6;
    int d = c & 63;
    const float* b = (s == 0) ? bq : (s == 1) ? bk : bv;
    float acc = 0.f;
#pragma unroll
    for (int h = 0; h < NH; h++)
        acc = fmaf(E[h * KEIG + k], b[h * DH + d], acc);
    g_bc[j] = acc * fw[k];
}

// ---------------------------------------------------------------------------
// Kernel A2: split x into fp16 hi/lo
// ---------------------------------------------------------------------------
__global__ __launch_bounds__(256)
void k_split_x(const float* __restrict__ x)
{
    size_t i = ((size_t)blockIdx.x * 256 + threadIdx.x) * 4;
    float4 v = *(const float4*)(x + i);
    __half h0 = __float2half_rn(v.x);
    __half h1 = __float2half_rn(v.y);
    __half h2 = __float2half_rn(v.z);
    __half h3 = __float2half_rn(v.w);
    __half l0 = __float2half_rn(v.x - __half2float(h0));
    __half l1 = __float2half_rn(v.y - __half2float(h1));
    __half l2 = __float2half_rn(v.z - __half2float(h2));
    __half l3 = __float2half_rn(v.w - __half2float(h3));
    uint2 ph, pl;
    ph.x = ((uint32_t)__half_as_ushort(h1) << 16) | __half_as_ushort(h0);
    ph.y = ((uint32_t)__half_as_ushort(h3) << 16) | __half_as_ushort(h2);
    pl.x = ((uint32_t)__half_as_ushort(l1) << 16) | __half_as_ushort(l0);
    pl.y = ((uint32_t)__half_as_ushort(l3) << 16) | __half_as_ushort(l2);
    *(uint2*)(g_xh + i) = ph;
    *(uint2*)(g_xl + i) = pl;
}

// ---------------------------------------------------------------------------
// Kernel A3: transpose g_Wc [k][n] -> fp16 hi/lo [n][k]
// ---------------------------------------------------------------------------
__global__ __launch_bounds__(256)
void k_wsplit()
{
    __shared__ float t[32][33];
    int tx = threadIdx.x & 31;
    int ty = threadIdx.x >> 5;
    int n0 = blockIdx.x * 32;
    int k0 = blockIdx.y * 32;
#pragma unroll
    for (int i = 0; i < 32; i += 8)
        t[ty + i][tx] = g_Wc[(size_t)(k0 + ty + i) * NC + (n0 + tx)];
    __syncthreads();
#pragma unroll
    for (int i = 0; i < 32; i += 8) {
        int n = n0 + ty + i;
        int k = k0 + tx;
        float v = t[tx][ty + i];
        __half h = __float2half_rn(v);
        __half l = __float2half_rn(v - __half2float(h));
        g_Wth[(size_t)n * KDIM + k] = h;
        g_Wtl[(size_t)n * KDIM + k] = l;
    }
}

// ---------------------------------------------------------------------------
// Kernel B: fused GEMM, double-buffered (the R13 structure that measured best).
//   Q,K tiles (bn < 2048): xh*Wh + xh*Wl + xl*Wh  (3 passes) -> fp32 g_QKf
//   V   tiles (bn >= 2048): xh*Wh                 (1 pass)   -> fp16 g_Vh
// CTA 128x128, 8 warps (2x4), warp tile 64x32, BK=32.
// ---------------------------------------------------------------------------
__global__ __launch_bounds__(256, 2)
void k_gemm_mma()
{
    extern __shared__ char smem[];
    const uint32_t sb = smem_u32(smem);
    const int tid  = threadIdx.x;
    const int lane = tid & 31;
    const int wid  = tid >> 5;
    const int bm = blockIdx.y * BM;
    const int bn = blockIdx.x * BN;
    const bool full3 = (bn < NCQK);

    const int mbase = (wid >> 2) * 64;
    const int nbase = (wid & 3) * 32;

    const __half* xh = g_xh  + (size_t)bm * KDIM;
    const __half* xl = g_xl  + (size_t)bm * KDIM;
    const __half* wh = g_Wth + (size_t)bn * KDIM;
    const __half* wl = g_Wtl + (size_t)bn * KDIM;

    auto load_chunk = [&](int st, int c) {
        uint32_t base = sb + st * STAGE;
        size_t koff = (size_t)c * BKC;
#pragma unroll
        for (int it = 0; it < 2; it++) {
            int idx = tid + it * 256;
            int row = idx >> 2, v = idx & 3;
            uint32_t so = SWZ64(row * 64 + v * 16);
            size_t go = (size_t)row * KDIM + koff + v * 8;
            cp16(base +         so, xh + go);
            cp16(base + 16384 + so, wh + go);
            if (full3) {
                cp16(base +  8192 + so, xl + go);
                cp16(base + 24576 + so, wl + go);
            }
        }
    };

    float acc[4][4][4];
#pragma unroll
    for (int i = 0; i < 4; i++)
#pragma unroll
        for (int j = 0; j < 4; j++)
#pragma unroll
            for (int r = 0; r < 4; r++) acc[i][j][r] = 0.f;

    load_chunk(0, 0);
    cp_commit();

    const int a_m = (lane & 15);
    const int a_h = (lane >> 4);
    const int b_n = ((lane >> 4) << 3) + (lane & 7);
    const int b_h = ((lane >> 3) & 1);

    for (int c = 0; c < NCH; c++) {
        if (c + 1 < NCH) { load_chunk((c + 1) & 1, c + 1); cp_commit(); }
        if (c + 1 < NCH) cp_wait<1>(); else cp_wait<0>();
        __syncthreads();

        uint32_t base = sb + (c & 1) * STAGE;
        uint32_t sAh = base;
        uint32_t sAl = base + 8192;
        uint32_t sBh = base + 16384;
        uint32_t sBl = base + 24576;

#pragma unroll
        for (int ks = 0; ks < 2; ks++) {
            uint32_t ah[4][4], bh[2][4];
            int av = ks * 2 + a_h;
            int bv = ks * 2 + b_h;
#pragma unroll
            for (int mb = 0; mb < 4; mb++) {
                int m = mbase + mb * 16 + a_m;
                ldsm4(ah[mb], sAh + SWZ64(m * 64 + av * 16));
            }
#pragma unroll
            for (int nb2 = 0; nb2 < 2; nb2++) {
                int n = nbase + nb2 * 16 + b_n;
                ldsm4(bh[nb2], sBh + SWZ64(n * 64 + bv * 16));
            }
            // pass 1: xh * Wh (always)
#pragma unroll
            for (int mb = 0; mb < 4; mb++)
#pragma unroll
                for (int nb = 0; nb < 4; nb++) {
                    const uint32_t* f = &bh[nb >> 1][(nb & 1) * 2];
                    mma16816(acc[mb][nb], ah[mb], f[0], f[1]);
                }
            if (full3) {
                // pass 2: xh * Wl
                uint32_t bl[2][4];
#pragma unroll
                for (int nb2 = 0; nb2 < 2; nb2++) {
                    int n = nbase + nb2 * 16 + b_n;
                    ldsm4(bl[nb2], sBl + SWZ64(n * 64 + bv * 16));
                }
#pragma unroll
                for (int mb = 0; mb < 4; mb++)
#pragma unroll
                    for (int nb = 0; nb < 4; nb++) {
                        const uint32_t* f = &bl[nb >> 1][(nb & 1) * 2];
                        mma16816(acc[mb][nb], ah[mb], f[0], f[1]);
                    }
                // pass 3: xl * Wh
                uint32_t al[4][4];
#pragma unroll
                for (int mb = 0; mb < 4; mb++) {
                    int m = mbase + mb * 16 + a_m;
                    ldsm4(al[mb], sAl + SWZ64(m * 64 + av * 16));
                }
#pragma unroll
                for (int mb = 0; mb < 4; mb++)
#pragma unroll
                    for (int nb = 0; nb < 4; nb++) {
                        const uint32_t* f = &bh[nb >> 1][(nb & 1) * 2];
                        mma16816(acc[mb][nb], al[mb], f[0], f[1]);
                    }
            }
        }
        __syncthreads();
    }

    // Epilogue
    if (full3) {
#pragma unroll
        for (int mb = 0; mb < 4; mb++) {
            int row = bm + mbase + mb * 16 + (lane >> 2);
#pragma unroll
            for (int nb = 0; nb < 4; nb++) {
                int col = bn + nbase + nb * 8 + (lane & 3) * 2;
                float b0 = g_bc[col], b1 = g_bc[col + 1];
                float2 v0 = make_float2(acc[mb][nb][0] + b0, acc[mb][nb][1] + b1);
                float2 v1 = make_float2(acc[mb][nb][2] + b0, acc[mb][nb][3] + b1);
                *(float2*)(g_QKf + (size_t)row * NCQK + col) = v0;
                *(float2*)(g_QKf + (size_t)(row + 8) * NCQK + col) = v1;
            }
        }
    } else {
        const int bnv = bn - NCQK;
#pragma unroll
        for (int mb = 0; mb < 4; mb++) {
            int row = bm + mbase + mb * 16 + (lane >> 2);
#pragma unroll
            for (int nb = 0; nb < 4; nb++) {
                int colv = bnv + nbase + nb * 8 + (lane & 3) * 2;
                float b0 = g_bc[NCQK + colv], b1 = g_bc[NCQK + colv + 1];
                __half2 h0 = __floats2half2_rn(acc[mb][nb][0] + b0, acc[mb][nb][1] + b1);
                __half2 h1 = __floats2half2_rn(acc[mb][nb][2] + b0, acc[mb][nb][3] + b1);
                *(__half2*)(g_Vh + (size_t)row * 1024 + colv) = h0;
                *(__half2*)(g_Vh + (size_t)(row + 8) * 1024 + colv) = h1;
            }
        }
    }
}

// ---------------------------------------------------------------------------
// Kernel C: per-token spectral attention, 2 tokens/block, float4 smem ops.
// Q,K from g_QKf (fp32, stride 2048); V from g_Vh (fp16, stride 1024).
// ---------------------------------------------------------------------------
#define TPB 2
__global__ __launch_bounds__(256)
void k_attn(const float* __restrict__ E, float* __restrict__ out)
{
    __shared__ float sQ[TPB][KEIG][68];
    __shared__ float sK[TPB][KEIG][68];
    __shared__ float sV[TPB][KEIG][68];
    __shared__ float sS[TPB][KEIG][17];
    __shared__ float sO[TPB][KEIG][68];
    __shared__ float sE[NH * KEIG];

    const int tid  = threadIdx.x;
    const int tok0 = blockIdx.x * TPB;

    // Q,K: TPB*512 float4 (4/thread)
#pragma unroll
    for (int v = tid; v < TPB * 512; v += 256) {
        int t = v >> 9;
        int r = v & 511;
        int mat = r >> 8;             // 0=Q 1=K
        int e   = r & 255;
        int k = e >> 4, dv = e & 15;
        float4 val = ((const float4*)(g_QKf + (size_t)(tok0 + t) * NCQK + mat * 1024))[e];
        float* dst = (mat == 0) ? &sQ[t][k][dv * 4] : &sK[t][k][dv * 4];
        *(float4*)dst = val;
    }
    // V: TPB*256 uint2 (4 halves each, 2/thread)
#pragma unroll
    for (int v = tid; v < TPB * 256; v += 256) {
        int t = v >> 8;
        int e = v & 255;
        int k = e >> 4, dv = e & 15;
        uint2 p = ((const uint2*)(g_Vh + (size_t)(tok0 + t) * 1024))[e];
        float2 ab = __half22float2(*(__half2*)&p.x);
        float2 cd = __half22float2(*(__half2*)&p.y);
        *(float4*)&sV[t][k][dv * 4] = make_float4(ab.x, ab.y, cd.x, cd.y);
    }
    sE[tid] = E[tid];
    __syncthreads();

    {
        int t = tid >> 7;
        int u = tid & 127;
#pragma unroll
        for (int pp = 0; pp < 2; pp++) {
            int p = u + pp * 128;
            int k = p >> 4, l = p & 15;
            float acc = 0.f;
#pragma unroll
            for (int dv = 0; dv < 16; dv++) {
                float4 q = *(const float4*)&sQ[t][k][dv * 4];
                float4 c = *(const float4*)&sK[t][l][dv * 4];
                acc = fmaf(q.x, c.x, acc);
                acc = fmaf(q.y, c.y, acc);
                acc = fmaf(q.z, c.z, acc);
                acc = fmaf(q.w, c.w, acc);
            }
            sS[t][k][l] = acc * 0.125f;
        }
    }
    __syncthreads();

    if (tid < TPB * KEIG) {
        int t = tid >> 4, k = tid & 15;
        float m = sS[t][k][0];
#pragma unroll
        for (int l = 1; l < KEIG; l++) m = fmaxf(m, sS[t][k][l]);
        float e[KEIG];
        float sum = 0.f;
#pragma unroll
        for (int l = 0; l < KEIG; l++) { e[l] = __expf(sS[t][k][l] - m); sum += e[l]; }
        float inv = 1.f / sum;
#pragma unroll
        for (int l = 0; l < KEIG; l++) sS[t][k][l] = e[l] * inv;
    }
    __syncthreads();

    {
        int t = tid >> 7;
        int u = tid & 127;
#pragma unroll
        for (int pp = 0; pp < 2; pp++) {
            int p = u + pp * 128;
            int k = p >> 4, dv = p & 15;
            float4 acc = make_float4(0.f, 0.f, 0.f, 0.f);
#pragma unroll
            for (int l = 0; l < KEIG; l++) {
                float a = sS[t][k][l];
                float4 v = *(const float4*)&sV[t][l][dv * 4];
                acc.x = fmaf(a, v.x, acc.x);
                acc.y = fmaf(a, v.y, acc.y);
                acc.z = fmaf(a, v.z, acc.z);
                acc.w = fmaf(a, v.w, acc.w);
            }
            *(float4*)&sO[t][k][dv * 4] = acc;
        }
    }
    __syncthreads();

    {
        int t = tid >> 7;
        int u = tid & 127;
#pragma unroll
        for (int pp = 0; pp < 2; pp++) {
            int p = u + pp * 128;
            int h = p >> 4, dv = p & 15;
            float4 acc = make_float4(0.f, 0.f, 0.f, 0.f);
#pragma unroll
            for (int k = 0; k < KEIG; k++) {
                float a = sE[h * KEIG + k];
                float4 v = *(const float4*)&sO[t][k][dv * 4];
                acc.x = fmaf(a, v.x, acc.x);
                acc.y = fmaf(a, v.y, acc.y);
                acc.z = fmaf(a, v.z, acc.z);
                acc.w = fmaf(a, v.w, acc.w);
            }
            ((float4*)(out + (size_t)(tok0 + t) * (NH * DH)))[h * 16 + dv] = acc;
        }
    }
}

// ---------------------------------------------------------------------------
extern "C" void kernel_launch(void* const* d_in, const int* in_sizes, int n_in,
                              void* d_out, int out_size)
{
    const float* x  = (const float*)d_in[0];
    const float* Wq = (const float*)d_in[1];
    const float* bq = (const float*)d_in[2];
    const float* Wk = (const float*)d_in[3];
    const float* bk = (const float*)d_in[4];
    const float* Wv = (const float*)d_in[5];
    const float* bv = (const float*)d_in[6];
    const float* E  = (const float*)d_in[7];
    const float* fw = (const float*)d_in[8];
    float* out = (float*)d_out;

    cudaFuncSetAttribute(k_gemm_mma, cudaFuncAttributeMaxDynamicSharedMemorySize,
                         GEMM_SMEM);

    k_transform_w<<<dim3(KDIM, 3), 256>>>(Wq, Wk, Wv, E, fw);
    k_transform_b<<<(NC + 255) / 256, 256>>>(bq, bk, bv, E, fw);
    k_split_x<<<(M_TOK * KDIM / 4) / 256, 256>>>(x);
    k_wsplit<<<dim3(NC / 32, KDIM / 32), 256>>>();
    k_gemm_mma<<<dim3(NC / BN, M_TOK / BM), 256, GEMM_SMEM>>>();
    k_attn<<<M_TOK / TPB, 256>>>(E, out);
}

// round 17
// speedup vs baseline: 1.0412x; 1.0150x over previous
#include <cuda_runtime.h>
#include <cuda_fp16.h>
#include <cstdint>

// Problem constants
#define D_MODEL 1024
#define NH      16
#define DH      64
#define KEIG    16
#define M_TOK   16384          // B * N = 4 * 4096
#define NC      3072           // 3 * NH * DH
#define NCQK    2048           // Qf|Kf columns kept in fp32
#define KDIM    1024

// GEMM tiling (mma.sync fp16 path)
#define BM 128
#define BN 128
#define BKC 32                 // K per chunk
#define NCH (KDIM / BKC)       // 32 chunks
#define STAGE 32768            // smem bytes per pipeline stage (4 tiles x 8KB)
#define GEMM_SMEM (2 * STAGE)  // 64 KB double buffered

// 64B-row swizzle
#define SWZ64(o) ((uint32_t)(o) ^ ((((uint32_t)(o)) >> 3) & 0x30u))

// ---------------------------------------------------------------------------
// Device scratch
// ---------------------------------------------------------------------------
__device__ float  g_Wc[(size_t)KDIM * NC];      // eigen-folded weights fp32 [k][n]
__device__ float  g_bc[NC];                      // eigen-folded bias
__device__ float  g_QKf[(size_t)M_TOK * NCQK];  // Qf|Kf fp32 per token
__device__ __half g_Vh[(size_t)M_TOK * 1024];   // Vf fp16 per token
__device__ __half g_xh[(size_t)M_TOK * KDIM];   // x hi fp16    [m][k]
__device__ __half g_xl[(size_t)M_TOK * KDIM];   // x lo fp16    [m][k]
__device__ __half g_Wth[(size_t)NC * KDIM];     // W^T hi fp16  [n][k]
__device__ __half g_Wtl[(size_t)NC * KDIM];     // W^T lo fp16  [n][k]

// ---------------------------------------------------------------------------
// PTX helpers (baseline PTX only — legal on non-'a' sm_103 target)
// ---------------------------------------------------------------------------
static __device__ __forceinline__ uint32_t smem_u32(const void* p) {
    uint32_t a;
    asm("{ .reg .u64 t; cvta.to.shared.u64 t, %1; cvt.u32.u64 %0, t; }"
        : "=r"(a) : "l"(p));
    return a;
}
static __device__ __forceinline__ void cp16(uint32_t saddr, const void* g) {
    asm volatile("cp.async.cg.shared.global [%0], [%1], 16;"
                 :: "r"(saddr), "l"(g));
}
static __device__ __forceinline__ void cp_commit() {
    asm volatile("cp.async.commit_group;" ::: "memory");
}
template <int N>
static __device__ __forceinline__ void cp_wait() {
    asm volatile("cp.async.wait_group %0;" :: "n"(N) : "memory");
}
static __device__ __forceinline__ void ldsm4(uint32_t* r, uint32_t addr) {
    asm volatile("ldmatrix.sync.aligned.m8n8.x4.shared.b16 {%0,%1,%2,%3}, [%4];"
                 : "=r"(r[0]), "=r"(r[1]), "=r"(r[2]), "=r"(r[3])
                 : "r"(addr));
}
static __device__ __forceinline__ void mma16816(float* d, const uint32_t* a,
                                                uint32_t b0, uint32_t b1) {
    asm volatile(
        "mma.sync.aligned.m16n8k16.row.col.f32.f16.f16.f32 "
        "{%0,%1,%2,%3}, {%4,%5,%6,%7}, {%8,%9}, {%0,%1,%2,%3};"
        : "+f"(d[0]), "+f"(d[1]), "+f"(d[2]), "+f"(d[3])
        : "r"(a[0]), "r"(a[1]), "r"(a[2]), "r"(a[3]), "r"(b0), "r"(b1));
}

// ---------------------------------------------------------------------------
// Kernel A1: fold eigenvectors + filter weights into fused weights
// ---------------------------------------------------------------------------
__global__ __launch_bounds__(256)
void k_transform_w(const float* __restrict__ Wq,
                   const float* __restrict__ Wk,
                   const float* __restrict__ Wv,
                   const float* __restrict__ E,
                   const float* __restrict__ fw)
{
    __shared__ float Ws[1024];
    __shared__ float Ek[16][16];

    const int r = blockIdx.x;
    const int s = blockIdx.y;
    const int tid = threadIdx.x;
    const float* W = (s == 0) ? Wq : (s == 1) ? Wk : Wv;

    ((float4*)Ws)[tid] = ((const float4*)(W + (size_t)r * 1024))[tid];
    {
        int h = tid >> 4, k = tid & 15;
        Ek[h][k] = E[tid] * fw[k];
    }
    __syncthreads();

    const int d = tid & 63;
    float* dst = g_Wc + (size_t)r * NC + s * 1024;
#pragma unroll
    for (int j = 0; j < 4; j++) {
        int k = (tid >> 6) + j * 4;
        float acc = 0.f;
#pragma unroll
        for (int h = 0; h < NH; h++)
            acc = fmaf(Ek[h][k], Ws[h * 64 + d], acc);
        dst[k * 64 + d] = acc;
    }
}

__global__ void k_transform_b(const float* __restrict__ bq,
                              const float* __restrict__ bk,
                              const float* __restrict__ bv,
                              const float* __restrict__ E,
                              const float* __restrict__ fw)
{
    int j = blockIdx.x * blockDim.x + threadIdx.x;
    if (j >= NC) return;
    int s = j >> 10;
    int c = j & 1023;
    int k = c >> 6;
    int d = c & 63;
    const float* b = (s == 0) ? bq : (s == 1) ? bk : bv;
    float acc = 0.f;
#pragma unroll
    for (int h = 0; h < NH; h++)
        acc = fmaf(E[h * KEIG + k], b[h * DH + d], acc);
    g_bc[j] = acc * fw[k];
}

// ---------------------------------------------------------------------------
// Kernel A2: split x into fp16 hi/lo
// ---------------------------------------------------------------------------
__global__ __launch_bounds__(256)
void k_split_x(const float* __restrict__ x)
{
    size_t i = ((size_t)blockIdx.x * 256 + threadIdx.x) * 4;
    float4 v = *(const float4*)(x + i);
    __half h0 = __float2half_rn(v.x);
    __half h1 = __float2half_rn(v.y);
    __half h2 = __float2half_rn(v.z);
    __half h3 = __float2half_rn(v.w);
    __half l0 = __float2half_rn(v.x - __half2float(h0));
    __half l1 = __float2half_rn(v.y - __half2float(h1));
    __half l2 = __float2half_rn(v.z - __half2float(h2));
    __half l3 = __float2half_rn(v.w - __half2float(h3));
    uint2 ph, pl;
    ph.x = ((uint32_t)__half_as_ushort(h1) << 16) | __half_as_ushort(h0);
    ph.y = ((uint32_t)__half_as_ushort(h3) << 16) | __half_as_ushort(h2);
    pl.x = ((uint32_t)__half_as_ushort(l1) << 16) | __half_as_ushort(l0);
    pl.y = ((uint32_t)__half_as_ushort(l3) << 16) | __half_as_ushort(l2);
    *(uint2*)(g_xh + i) = ph;
    *(uint2*)(g_xl + i) = pl;
}

// ---------------------------------------------------------------------------
// Kernel A3: transpose g_Wc [k][n] -> fp16 hi/lo [n][k]
// ---------------------------------------------------------------------------
__global__ __launch_bounds__(256)
void k_wsplit()
{
    __shared__ float t[32][33];
    int tx = threadIdx.x & 31;
    int ty = threadIdx.x >> 5;
    int n0 = blockIdx.x * 32;
    int k0 = blockIdx.y * 32;
#pragma unroll
    for (int i = 0; i < 32; i += 8)
        t[ty + i][tx] = g_Wc[(size_t)(k0 + ty + i) * NC + (n0 + tx)];
    __syncthreads();
#pragma unroll
    for (int i = 0; i < 32; i += 8) {
        int n = n0 + ty + i;
        int k = k0 + tx;
        float v = t[tx][ty + i];
        __half h = __float2half_rn(v);
        __half l = __float2half_rn(v - __half2float(h));
        g_Wth[(size_t)n * KDIM + k] = h;
        g_Wtl[(size_t)n * KDIM + k] = l;
    }
}

// ---------------------------------------------------------------------------
// Kernel B: fused GEMM, double-buffered (R13/R15 structure — measured best).
//   Q,K tiles (bn < 2048): xh*Wh + xh*Wl + xl*Wh  (3 passes) -> fp32 g_QKf
//   V   tiles (bn >= 2048): xh*Wh                 (1 pass)   -> fp16 g_Vh
// ---------------------------------------------------------------------------
__global__ __launch_bounds__(256, 2)
void k_gemm_mma()
{
    extern __shared__ char smem[];
    const uint32_t sb = smem_u32(smem);
    const int tid  = threadIdx.x;
    const int lane = tid & 31;
    const int wid  = tid >> 5;
    const int bm = blockIdx.y * BM;
    const int bn = blockIdx.x * BN;
    const bool full3 = (bn < NCQK);

    const int mbase = (wid >> 2) * 64;
    const int nbase = (wid & 3) * 32;

    const __half* xh = g_xh  + (size_t)bm * KDIM;
    const __half* xl = g_xl  + (size_t)bm * KDIM;
    const __half* wh = g_Wth + (size_t)bn * KDIM;
    const __half* wl = g_Wtl + (size_t)bn * KDIM;

    auto load_chunk = [&](int st, int c) {
        uint32_t base = sb + st * STAGE;
        size_t koff = (size_t)c * BKC;
#pragma unroll
        for (int it = 0; it < 2; it++) {
            int idx = tid + it * 256;
            int row = idx >> 2, v = idx & 3;
            uint32_t so = SWZ64(row * 64 + v * 16);
            size_t go = (size_t)row * KDIM + koff + v * 8;
            cp16(base +         so, xh + go);
            cp16(base + 16384 + so, wh + go);
            if (full3) {
                cp16(base +  8192 + so, xl + go);
                cp16(base + 24576 + so, wl + go);
            }
        }
    };

    float acc[4][4][4];
#pragma unroll
    for (int i = 0; i < 4; i++)
#pragma unroll
        for (int j = 0; j < 4; j++)
#pragma unroll
            for (int r = 0; r < 4; r++) acc[i][j][r] = 0.f;

    load_chunk(0, 0);
    cp_commit();

    const int a_m = (lane & 15);
    const int a_h = (lane >> 4);
    const int b_n = ((lane >> 4) << 3) + (lane & 7);
    const int b_h = ((lane >> 3) & 1);

    for (int c = 0; c < NCH; c++) {
        if (c + 1 < NCH) { load_chunk((c + 1) & 1, c + 1); cp_commit(); }
        if (c + 1 < NCH) cp_wait<1>(); else cp_wait<0>();
        __syncthreads();

        uint32_t base = sb + (c & 1) * STAGE;
        uint32_t sAh = base;
        uint32_t sAl = base + 8192;
        uint32_t sBh = base + 16384;
        uint32_t sBl = base + 24576;

#pragma unroll
        for (int ks = 0; ks < 2; ks++) {
            uint32_t ah[4][4], bh[2][4];
            int av = ks * 2 + a_h;
            int bv = ks * 2 + b_h;
#pragma unroll
            for (int mb = 0; mb < 4; mb++) {
                int m = mbase + mb * 16 + a_m;
                ldsm4(ah[mb], sAh + SWZ64(m * 64 + av * 16));
            }
#pragma unroll
            for (int nb2 = 0; nb2 < 2; nb2++) {
                int n = nbase + nb2 * 16 + b_n;
                ldsm4(bh[nb2], sBh + SWZ64(n * 64 + bv * 16));
            }
            // pass 1: xh * Wh (always)
#pragma unroll
            for (int mb = 0; mb < 4; mb++)
#pragma unroll
                for (int nb = 0; nb < 4; nb++) {
                    const uint32_t* f = &bh[nb >> 1][(nb & 1) * 2];
                    mma16816(acc[mb][nb], ah[mb], f[0], f[1]);
                }
            if (full3) {
                // pass 2: xh * Wl
                uint32_t bl[2][4];
#pragma unroll
                for (int nb2 = 0; nb2 < 2; nb2++) {
                    int n = nbase + nb2 * 16 + b_n;
                    ldsm4(bl[nb2], sBl + SWZ64(n * 64 + bv * 16));
                }
#pragma unroll
                for (int mb = 0; mb < 4; mb++)
#pragma unroll
                    for (int nb = 0; nb < 4; nb++) {
                        const uint32_t* f = &bl[nb >> 1][(nb & 1) * 2];
                        mma16816(acc[mb][nb], ah[mb], f[0], f[1]);
                    }
                // pass 3: xl * Wh
                uint32_t al[4][4];
#pragma unroll
                for (int mb = 0; mb < 4; mb++) {
                    int m = mbase + mb * 16 + a_m;
                    ldsm4(al[mb], sAl + SWZ64(m * 64 + av * 16));
                }
#pragma unroll
                for (int mb = 0; mb < 4; mb++)
#pragma unroll
                    for (int nb = 0; nb < 4; nb++) {
                        const uint32_t* f = &bh[nb >> 1][(nb & 1) * 2];
                        mma16816(acc[mb][nb], al[mb], f[0], f[1]);
                    }
            }
        }
        __syncthreads();
    }

    // Epilogue
    if (full3) {
#pragma unroll
        for (int mb = 0; mb < 4; mb++) {
            int row = bm + mbase + mb * 16 + (lane >> 2);
#pragma unroll
            for (int nb = 0; nb < 4; nb++) {
                int col = bn + nbase + nb * 8 + (lane & 3) * 2;
                float b0 = g_bc[col], b1 = g_bc[col + 1];
                float2 v0 = make_float2(acc[mb][nb][0] + b0, acc[mb][nb][1] + b1);
                float2 v1 = make_float2(acc[mb][nb][2] + b0, acc[mb][nb][3] + b1);
                *(float2*)(g_QKf + (size_t)row * NCQK + col) = v0;
                *(float2*)(g_QKf + (size_t)(row + 8) * NCQK + col) = v1;
            }
        }
    } else {
        const int bnv = bn - NCQK;
#pragma unroll
        for (int mb = 0; mb < 4; mb++) {
            int row = bm + mbase + mb * 16 + (lane >> 2);
#pragma unroll
            for (int nb = 0; nb < 4; nb++) {
                int colv = bnv + nbase + nb * 8 + (lane & 3) * 2;
                float b0 = g_bc[NCQK + colv], b1 = g_bc[NCQK + colv + 1];
                __half2 h0 = __floats2half2_rn(acc[mb][nb][0] + b0, acc[mb][nb][1] + b1);
                __half2 h1 = __floats2half2_rn(acc[mb][nb][2] + b0, acc[mb][nb][3] + b1);
                *(__half2*)(g_Vh + (size_t)row * 1024 + colv) = h0;
                *(__half2*)(g_Vh + (size_t)(row + 8) * 1024 + colv) = h1;
            }
        }
    }
}

// ---------------------------------------------------------------------------
// Kernel C (v3): per-token spectral attention with reassociated epilogue:
//   out = E·(softmax(QK^T)·V) = (E·S)·V,  M = E·S is only 16x16.
// Removes the sO stage + one __syncthreads; 2 tokens/block, float4 smem ops.
// ---------------------------------------------------------------------------
#define TPB 2
__global__ __launch_bounds__(256)
void k_attn(const float* __restrict__ E, float* __restrict__ out)
{
    __shared__ float sQ[TPB][KEIG][68];
    __shared__ float sK[TPB][KEIG][68];
    __shared__ float sV[TPB][KEIG][68];
    __shared__ float sS[TPB][KEIG][17];
    __shared__ float sM[TPB][NH][17];
    __shared__ float sE[NH * KEIG];

    const int tid  = threadIdx.x;
    const int tok0 = blockIdx.x * TPB;

    // Q,K: TPB*512 float4 (4/thread)
#pragma unroll
    for (int v = tid; v < TPB * 512; v += 256) {
        int t = v >> 9;
        int r = v & 511;
        int mat = r >> 8;             // 0=Q 1=K
        int e   = r & 255;
        int k = e >> 4, dv = e & 15;
        float4 val = ((const float4*)(g_QKf + (size_t)(tok0 + t) * NCQK + mat * 1024))[e];
        float* dst = (mat == 0) ? &sQ[t][k][dv * 4] : &sK[t][k][dv * 4];
        *(float4*)dst = val;
    }
    // V: TPB*256 uint2 (4 halves each, 2/thread)
#pragma unroll
    for (int v = tid; v < TPB * 256; v += 256) {
        int t = v >> 8;
        int e = v & 255;
        int k = e >> 4, dv = e & 15;
        uint2 p = ((const uint2*)(g_Vh + (size_t)(tok0 + t) * 1024))[e];
        float2 ab = __half22float2(*(__half2*)&p.x);
        float2 cd = __half22float2(*(__half2*)&p.y);
        *(float4*)&sV[t][k][dv * 4] = make_float4(ab.x, ab.y, cd.x, cd.y);
    }
    sE[tid] = E[tid];
    __syncthreads();

    // scores: 2 (k,l) pairs per thread
    {
        int t = tid >> 7;
        int u = tid & 127;
#pragma unroll
        for (int pp = 0; pp < 2; pp++) {
            int p = u + pp * 128;
            int k = p >> 4, l = p & 15;
            float acc = 0.f;
#pragma unroll
            for (int dv = 0; dv < 16; dv++) {
                float4 q = *(const float4*)&sQ[t][k][dv * 4];
                float4 c = *(const float4*)&sK[t][l][dv * 4];
                acc = fmaf(q.x, c.x, acc);
                acc = fmaf(q.y, c.y, acc);
                acc = fmaf(q.z, c.z, acc);
                acc = fmaf(q.w, c.w, acc);
            }
            sS[t][k][l] = acc * 0.125f;
        }
    }
    __syncthreads();

    // softmax rows
    if (tid < TPB * KEIG) {
        int t = tid >> 4, k = tid & 15;
        float m = sS[t][k][0];
#pragma unroll
        for (int l = 1; l < KEIG; l++) m = fmaxf(m, sS[t][k][l]);
        float e[KEIG];
        float sum = 0.f;
#pragma unroll
        for (int l = 0; l < KEIG; l++) { e[l] = __expf(sS[t][k][l] - m); sum += e[l]; }
        float inv = 1.f / sum;
#pragma unroll
        for (int l = 0; l < KEIG; l++) sS[t][k][l] = e[l] * inv;
    }
    __syncthreads();

    // M[h][l] = sum_k E[h,k] * S[k][l]  (16x16 per token; 2 items/thread)
    {
        int t = tid >> 7;
        int u = tid & 127;
#pragma unroll
        for (int pp = 0; pp < 2; pp++) {
            int p = u + pp * 128;
            int h = p >> 4, l = p & 15;
            float acc = 0.f;
#pragma unroll
            for (int k = 0; k < KEIG; k++)
                acc = fmaf(sE[h * KEIG + k], sS[t][k][l], acc);
            sM[t][h][l] = acc;
        }
    }
    __syncthreads();

    // out[h][d] = sum_l M[h][l] * V[l][d]  (straight to gmem; 2 float4/thread)
    {
        int t = tid >> 7;
        int u = tid & 127;
#pragma unroll
        for (int pp = 0; pp < 2; pp++) {
            int p = u + pp * 128;
            int h = p >> 4, dv = p & 15;
            float4 acc = make_float4(0.f, 0.f, 0.f, 0.f);
#pragma unroll
            for (int l = 0; l < KEIG; l++) {
                float a = sM[t][h][l];
                float4 v = *(const float4*)&sV[t][l][dv * 4];
                acc.x = fmaf(a, v.x, acc.x);
                acc.y = fmaf(a, v.y, acc.y);
                acc.z = fmaf(a, v.z, acc.z);
                acc.w = fmaf(a, v.w, acc.w);
            }
            ((float4*)(out + (size_t)(tok0 + t) * (NH * DH)))[h * 16 + dv] = acc;
        }
    }
}

// ---------------------------------------------------------------------------
extern "C" void kernel_launch(void* const* d_in, const int* in_sizes, int n_in,
                              void* d_out, int out_size)
{
    const float* x  = (const float*)d_in[0];
    const float* Wq = (const float*)d_in[1];
    const float* bq = (const float*)d_in[2];
    const float* Wk = (const float*)d_in[3];
    const float* bk = (const float*)d_in[4];
    const float* Wv = (const float*)d_in[5];
    const float* bv = (const float*)d_in[6];
    const float* E  = (const float*)d_in[7];
    const float* fw = (const float*)d_in[8];
    float* out = (float*)d_out;

    cudaFuncSetAttribute(k_gemm_mma, cudaFuncAttributeMaxDynamicSharedMemorySize,
                         GEMM_SMEM);

    k_transform_w<<<dim3(KDIM, 3), 256>>>(Wq, Wk, Wv, E, fw);
    k_transform_b<<<(NC + 255) / 256, 256>>>(bq, bk, bv, E, fw);
    k_split_x<<<(M_TOK * KDIM / 4) / 256, 256>>>(x);
    k_wsplit<<<dim3(NC / 32, KDIM / 32), 256>>>();
    k_gemm_mma<<<dim3(NC / BN, M_TOK / BM), 256, GEMM_SMEM>>>();
    k_attn<<<M_TOK / TPB, 256>>>(E, out);
}